// round 2
// baseline (speedup 1.0000x reference)
#include <cuda_runtime.h>

#define D 128
#define DV 32          // D / 4 (float4)
#define EPS 1e-5f
#define NT 32          // nodes per MLP block
#define PAD 36         // k-major tile pitch (16B-aligned, conflict-tolerable)
#define MAXN 50000

// Device scratch (allocation-free rule: __device__ globals)
__device__ float4 g_agg4[(size_t)MAXN * DV];   // aggregated messages [N][D]
__device__ float4 g_hln4[(size_t)MAXN * DV];   // post-LayerNorm h    [N][D]
__device__ float  g_colsum[D];
__device__ float  g_colsumsq[D];
__device__ float  g_mul[D];
__device__ float  g_sub[D];

// ---------------------------------------------------------------------------
// K0: zero agg + stats accumulators
// ---------------------------------------------------------------------------
__global__ void k_zero(int total4) {
    int i = blockIdx.x * blockDim.x + threadIdx.x;
    if (i < total4) g_agg4[i] = make_float4(0.f, 0.f, 0.f, 0.f);
    if (i < D) { g_colsum[i] = 0.f; g_colsumsq[i] = 0.f; }
}

// ---------------------------------------------------------------------------
// K1: scatter-add messages. One warp per edge, float4 per lane (32*16B = 512B row)
// edge_index is int32 (JAX default x64-disabled downcasts jnp.int64 -> int32).
// ---------------------------------------------------------------------------
__global__ void k_scatter(const float* __restrict__ nh,
                          const float* __restrict__ eh,
                          const int* __restrict__ ei,
                          int E) {
    int gw   = (blockIdx.x * blockDim.x + threadIdx.x) >> 5;
    int lane = threadIdx.x & 31;
    if (gw >= E) return;
    int src = ei[gw];
    int dst = ei[E + gw];
    const float4* nh4 = (const float4*)(nh + (size_t)src * D);
    const float4* eh4 = (const float4*)(eh + (size_t)gw * D);
    float4 a = nh4[lane];
    float4 b = eh4[lane];
    float4 v = make_float4(a.x + b.x, a.y + b.y, a.z + b.z, a.w + b.w);
    float* p = (float*)(g_agg4 + (size_t)dst * DV) + lane * 4;
    asm volatile("red.global.add.v4.f32 [%0], {%1, %2, %3, %4};"
                 :: "l"(p), "f"(v.x), "f"(v.y), "f"(v.z), "f"(v.w)
                 : "memory");
}

// ---------------------------------------------------------------------------
// K2: fused 2-layer MLP + LayerNorm + GraphNorm column-stat accumulation.
// Block = 256 threads, NT=32 nodes. SMEM: W (16384 f), agg tile k-major
// (128 x PAD), h1 tile k-major (128 x PAD). 102400 bytes dynamic.
// ---------------------------------------------------------------------------
__global__ void k_mlp(const float* __restrict__ w1, const float* __restrict__ b1,
                      const float* __restrict__ w2, const float* __restrict__ b2,
                      const float* __restrict__ lng, const float* __restrict__ lnb,
                      int N) {
    extern __shared__ float smem[];
    float* sW = smem;                // 16384 floats (also reused as sS [32][128])
    float* sA = smem + 16384;        // 128 * PAD = 4608
    float* sH = smem + 16384 + 128 * PAD;  // 4608

    const int t = threadIdx.x;                 // 0..255
    const int nodeBase = blockIdx.x * NT;

    // ---- load agg tile (transposed to k-major) ----
    {
        int n  = t >> 3;             // 0..31
        int k0 = (t & 7) * 16;       // 0..112
        int gn = nodeBase + n;
        #pragma unroll
        for (int i = 0; i < 4; ++i) {
            float4 v = make_float4(0.f, 0.f, 0.f, 0.f);
            if (gn < N) v = g_agg4[(size_t)gn * DV + (k0 >> 2) + i];
            int kk = k0 + i * 4;
            sA[(kk + 0) * PAD + n] = v.x;
            sA[(kk + 1) * PAD + n] = v.y;
            sA[(kk + 2) * PAD + n] = v.z;
            sA[(kk + 3) * PAD + n] = v.w;
        }
    }
    // ---- load W1 ----
    for (int i = t; i < 4096; i += 256)
        ((float4*)sW)[i] = ((const float4*)w1)[i];
    __syncthreads();

    const int j  = t & 127;          // output channel
    const int nh = t >> 7;           // node half: 0 or 1 (16 nodes each)

    float acc[16];
    #pragma unroll
    for (int i = 0; i < 16; ++i) acc[i] = 0.f;

    // ---- phase 1: h1 = agg @ W1 ----
    for (int k = 0; k < D; ++k) {
        float wv = sW[k * D + j];
        const float4* ap = (const float4*)(sA + k * PAD + nh * 16);
        #pragma unroll
        for (int v = 0; v < 4; ++v) {
            float4 a = ap[v];
            acc[v*4+0] = fmaf(a.x, wv, acc[v*4+0]);
            acc[v*4+1] = fmaf(a.y, wv, acc[v*4+1]);
            acc[v*4+2] = fmaf(a.z, wv, acc[v*4+2]);
            acc[v*4+3] = fmaf(a.w, wv, acc[v*4+3]);
        }
    }
    {
        float bb = b1[j];
        #pragma unroll
        for (int i = 0; i < 16; ++i)
            sH[j * PAD + nh * 16 + i] = fmaxf(acc[i] + bb, 0.f);
    }
    __syncthreads();

    // ---- load W2 (overwrites W1) ----
    for (int i = t; i < 4096; i += 256)
        ((float4*)sW)[i] = ((const float4*)w2)[i];
    __syncthreads();

    #pragma unroll
    for (int i = 0; i < 16; ++i) acc[i] = 0.f;

    // ---- phase 2: h2 = relu(h1) @ W2 ----
    for (int k = 0; k < D; ++k) {
        float wv = sW[k * D + j];
        const float4* hp = (const float4*)(sH + k * PAD + nh * 16);
        #pragma unroll
        for (int v = 0; v < 4; ++v) {
            float4 a = hp[v];
            acc[v*4+0] = fmaf(a.x, wv, acc[v*4+0]);
            acc[v*4+1] = fmaf(a.y, wv, acc[v*4+1]);
            acc[v*4+2] = fmaf(a.z, wv, acc[v*4+2]);
            acc[v*4+3] = fmaf(a.w, wv, acc[v*4+3]);
        }
    }
    float b2v = b2[j];
    __syncthreads();                 // done reading sW (W2) -> reuse as sS

    float* sS = sW;                  // [32][128] node-major h2
    #pragma unroll
    for (int i = 0; i < 16; ++i)
        sS[(nh * 16 + i) * D + j] = acc[i] + b2v;
    __syncthreads();

    // ---- LayerNorm per node (warp per node, 4 nodes/warp) + column partials ----
    int wid  = t >> 5;
    int lane = t & 31;
    float* sPartS = sA;              // [8][128]
    float* sPartQ = sA + 8 * D;      // [8][128]  (fits: 2048 <= 4608)

    float colS[4] = {0.f, 0.f, 0.f, 0.f};
    float colQ[4] = {0.f, 0.f, 0.f, 0.f};

    #pragma unroll
    for (int r = 0; r < 4; ++r) {
        int n  = wid + r * 8;        // 0..31
        int gn = nodeBase + n;
        float v0 = sS[n * D + lane];
        float v1 = sS[n * D + lane + 32];
        float v2 = sS[n * D + lane + 64];
        float v3 = sS[n * D + lane + 96];
        float s = v0 + v1 + v2 + v3;
        float q = v0*v0 + v1*v1 + v2*v2 + v3*v3;
        #pragma unroll
        for (int o = 16; o; o >>= 1) {
            s += __shfl_xor_sync(0xFFFFFFFFu, s, o);
            q += __shfl_xor_sync(0xFFFFFFFFu, q, o);
        }
        float mu  = s * (1.f / 128.f);
        float var = q * (1.f / 128.f) - mu * mu;
        float inv = rsqrtf(var + EPS);
        if (gn < N) {
            float y0 = (v0 - mu) * inv * lng[lane]      + lnb[lane];
            float y1 = (v1 - mu) * inv * lng[lane + 32] + lnb[lane + 32];
            float y2 = (v2 - mu) * inv * lng[lane + 64] + lnb[lane + 64];
            float y3 = (v3 - mu) * inv * lng[lane + 96] + lnb[lane + 96];
            float* hp = (float*)(g_hln4 + (size_t)gn * DV);
            hp[lane]      = y0;
            hp[lane + 32] = y1;
            hp[lane + 64] = y2;
            hp[lane + 96] = y3;
            colS[0] += y0; colQ[0] += y0 * y0;
            colS[1] += y1; colQ[1] += y1 * y1;
            colS[2] += y2; colQ[2] += y2 * y2;
            colS[3] += y3; colQ[3] += y3 * y3;
        }
    }
    #pragma unroll
    for (int qq = 0; qq < 4; ++qq) {
        sPartS[wid * D + lane + 32 * qq] = colS[qq];
        sPartQ[wid * D + lane + 32 * qq] = colQ[qq];
    }
    __syncthreads();
    if (t < D) {
        float s = 0.f, q = 0.f;
        #pragma unroll
        for (int w8 = 0; w8 < 8; ++w8) {
            s += sPartS[w8 * D + t];
            q += sPartQ[w8 * D + t];
        }
        atomicAdd(&g_colsum[t], s);
        atomicAdd(&g_colsumsq[t], q);
    }
}

// ---------------------------------------------------------------------------
// K3: finalize GraphNorm stats (1 block, 128 threads)
// ---------------------------------------------------------------------------
__global__ void k_statfin(const float* __restrict__ gnw,
                          const float* __restrict__ gnms,
                          float invN) {
    int c = threadIdx.x;
    float gmu = g_colsum[c] * invN;
    float e2  = g_colsumsq[c] * invN;
    float ms  = gnms[c];
    // E[(h - ms*gmu)^2] = E[h^2] - 2*ms*gmu^2 + ms^2*gmu^2
    float gvar = e2 - 2.f * ms * gmu * gmu + ms * ms * gmu * gmu;
    g_mul[c] = rsqrtf(gvar + EPS) * gnw[c];
    g_sub[c] = ms * gmu;
}

// ---------------------------------------------------------------------------
// K4: out = relu((hln - sub) * mul + gn_b) + node_hidden
// ---------------------------------------------------------------------------
__global__ void k_final(const float* __restrict__ nh,
                        const float* __restrict__ gnb,
                        float* __restrict__ out,
                        int total4) {
    int i = blockIdx.x * blockDim.x + threadIdx.x;
    if (i >= total4) return;
    int c4 = (i & (DV - 1)) * 4;
    float4 h = g_hln4[i];
    float4 x = ((const float4*)nh)[i];
    float4 o;
    o.x = fmaxf((h.x - g_sub[c4 + 0]) * g_mul[c4 + 0] + gnb[c4 + 0], 0.f) + x.x;
    o.y = fmaxf((h.y - g_sub[c4 + 1]) * g_mul[c4 + 1] + gnb[c4 + 1], 0.f) + x.y;
    o.z = fmaxf((h.z - g_sub[c4 + 2]) * g_mul[c4 + 2] + gnb[c4 + 2], 0.f) + x.z;
    o.w = fmaxf((h.w - g_sub[c4 + 3]) * g_mul[c4 + 3] + gnb[c4 + 3], 0.f) + x.w;
    ((float4*)out)[i] = o;
}

// ---------------------------------------------------------------------------
extern "C" void kernel_launch(void* const* d_in, const int* in_sizes, int n_in,
                              void* d_out, int out_size) {
    const float* nh   = (const float*)d_in[0];
    const float* eh   = (const float*)d_in[1];
    const float* w1   = (const float*)d_in[2];
    const float* b1   = (const float*)d_in[3];
    const float* w2   = (const float*)d_in[4];
    const float* b2   = (const float*)d_in[5];
    const float* lng  = (const float*)d_in[6];
    const float* lnb  = (const float*)d_in[7];
    const float* gnw  = (const float*)d_in[8];
    const float* gnb  = (const float*)d_in[9];
    const float* gnms = (const float*)d_in[10];
    const int*   ei   = (const int*)d_in[11];

    int N = in_sizes[0] / D;
    int E = in_sizes[1] / D;
    int total4 = N * DV;

    const int SMEM_BYTES = (16384 + 2 * 128 * PAD) * (int)sizeof(float);  // 102400
    cudaFuncSetAttribute(k_mlp, cudaFuncAttributeMaxDynamicSharedMemorySize, SMEM_BYTES);

    k_zero<<<(total4 + 255) / 256, 256>>>(total4);
    k_scatter<<<(E + 7) / 8, 256>>>(nh, eh, ei, E);
    k_mlp<<<(N + NT - 1) / NT, 256, SMEM_BYTES>>>(w1, b1, w2, b2, lng, lnb, N);
    k_statfin<<<1, 128>>>(gnw, gnms, 1.f / (float)N);
    k_final<<<(total4 + 255) / 256, 256>>>(nh, gnb, (float*)d_out, total4);
}

// round 3
// speedup vs baseline: 1.8300x; 1.8300x over previous
#include <cuda_runtime.h>
#include <cuda_bf16.h>
#include <cstdint>

#define D 128
#define DV 32          // D / 4 (float4)
#define EPS 1e-5f
#define NT 32          // nodes per MLP block
#define PA 136         // bf16 tile pitch (272B rows -> conflict-free LDSM)
#define PS 132         // f32 h2 tile pitch
#define MAXN 50000

// Device scratch (allocation-free rule: __device__ globals)
__device__ float4 g_agg4[(size_t)MAXN * DV];   // aggregated messages [N][D]
__device__ float4 g_hln4[(size_t)MAXN * DV];   // post-LayerNorm h    [N][D]
__device__ float  g_colsum[D];
__device__ float  g_colsumsq[D];
__device__ float  g_mul[D];
__device__ float  g_sub[D];
// Pre-packed weights in B-fragment register order:
// [kt(8)][nsub(16)][lane(32)] -> uint4{bhi0,bhi1,blo0,blo1}
__device__ uint4  g_w1p[4096];
__device__ uint4  g_w2p[4096];

// ---------------------------------------------------------------------------
// helpers
// ---------------------------------------------------------------------------
__device__ __forceinline__ uint32_t smem_u32(const void* p) {
    return (uint32_t)__cvta_generic_to_shared(p);
}

__device__ __forceinline__ void ldsm_x4(uint32_t* r, uint32_t addr) {
    asm volatile("ldmatrix.sync.aligned.m8n8.x4.shared.b16 {%0,%1,%2,%3}, [%4];"
                 : "=r"(r[0]), "=r"(r[1]), "=r"(r[2]), "=r"(r[3]) : "r"(addr));
}

__device__ __forceinline__ void mma16816(float* d, const uint32_t* a,
                                         const uint32_t* b) {
    asm volatile(
        "mma.sync.aligned.m16n8k16.row.col.f32.bf16.bf16.f32 "
        "{%0,%1,%2,%3}, {%4,%5,%6,%7}, {%8,%9}, {%0,%1,%2,%3};"
        : "+f"(d[0]), "+f"(d[1]), "+f"(d[2]), "+f"(d[3])
        : "r"(a[0]), "r"(a[1]), "r"(a[2]), "r"(a[3]), "r"(b[0]), "r"(b[1]));
}

// pack two floats into bf16x2 (hi parts); residuals returned via ra/rb
__device__ __forceinline__ uint32_t bf2_hi(float a, float b, float& ra, float& rb) {
    __nv_bfloat16 ha = __float2bfloat16_rn(a);
    __nv_bfloat16 hb = __float2bfloat16_rn(b);
    ra = a - __bfloat162float(ha);
    rb = b - __bfloat162float(hb);
    __nv_bfloat162 h; h.x = ha; h.y = hb;
    return *(uint32_t*)&h;
}
__device__ __forceinline__ uint32_t bf2(float a, float b) {
    __nv_bfloat162 h; h.x = __float2bfloat16_rn(a); h.y = __float2bfloat16_rn(b);
    return *(uint32_t*)&h;
}

// ---------------------------------------------------------------------------
// K0: zero agg + stats accumulators
// ---------------------------------------------------------------------------
__global__ void k_zero(int total4) {
    int i = blockIdx.x * blockDim.x + threadIdx.x;
    if (i < total4) g_agg4[i] = make_float4(0.f, 0.f, 0.f, 0.f);
    if (i < D) { g_colsum[i] = 0.f; g_colsumsq[i] = 0.f; }
}

// ---------------------------------------------------------------------------
// Kp: pack W1/W2 into bf16 hi/lo B-fragment order (4096 threads)
// ---------------------------------------------------------------------------
__global__ void k_prep(const float* __restrict__ w1, const float* __restrict__ w2) {
    int idx = blockIdx.x * blockDim.x + threadIdx.x;
    if (idx >= 4096) return;
    int lane = idx & 31;
    int nsub = (idx >> 5) & 15;
    int kt   = idx >> 9;
    int k0 = kt * 16 + (lane & 3) * 2;
    int n  = nsub * 8 + (lane >> 2);

    {
        float a0 = w1[(k0    ) * D + n], a1 = w1[(k0 + 1) * D + n];
        float a2 = w1[(k0 + 8) * D + n], a3 = w1[(k0 + 9) * D + n];
        float r0, r1, r2, r3;
        uint4 q;
        q.x = bf2_hi(a0, a1, r0, r1);
        q.y = bf2_hi(a2, a3, r2, r3);
        q.z = bf2(r0, r1);
        q.w = bf2(r2, r3);
        g_w1p[idx] = q;
    }
    {
        float a0 = w2[(k0    ) * D + n], a1 = w2[(k0 + 1) * D + n];
        float a2 = w2[(k0 + 8) * D + n], a3 = w2[(k0 + 9) * D + n];
        float r0, r1, r2, r3;
        uint4 q;
        q.x = bf2_hi(a0, a1, r0, r1);
        q.y = bf2_hi(a2, a3, r2, r3);
        q.z = bf2(r0, r1);
        q.w = bf2(r2, r3);
        g_w2p[idx] = q;
    }
}

// ---------------------------------------------------------------------------
// K1: scatter-add messages (unchanged). edge_index is int32.
// ---------------------------------------------------------------------------
__global__ void k_scatter(const float* __restrict__ nh,
                          const float* __restrict__ eh,
                          const int* __restrict__ ei,
                          int E) {
    int gw   = (blockIdx.x * blockDim.x + threadIdx.x) >> 5;
    int lane = threadIdx.x & 31;
    if (gw >= E) return;
    int src = ei[gw];
    int dst = ei[E + gw];
    const float4* nh4 = (const float4*)(nh + (size_t)src * D);
    const float4* eh4 = (const float4*)(eh + (size_t)gw * D);
    float4 a = nh4[lane];
    float4 b = eh4[lane];
    float4 v = make_float4(a.x + b.x, a.y + b.y, a.z + b.z, a.w + b.w);
    float* p = (float*)(g_agg4 + (size_t)dst * DV) + lane * 4;
    asm volatile("red.global.add.v4.f32 [%0], {%1, %2, %3, %4};"
                 :: "l"(p), "f"(v.x), "f"(v.y), "f"(v.z), "f"(v.w)
                 : "memory");
}

// ---------------------------------------------------------------------------
// K2: tensor-core MLP (3-term bf16 split) + LayerNorm + GraphNorm partials.
// Block = 256 threads (8 warps), 32 nodes. Warp w: mh = w&1 (16-row half),
// nq = w>>2? no: nq = w>>1 (32-col quarter). Each warp: 16x32 output tile.
// SMEM bytes:
//   [0      ,  8704) sAhi  32 x PA bf16
//   [8704   , 17408) sAlo
//   [17408  , 26112) sHhi
//   [26112  , 34816) sHlo
//   [34816  , 51712) sS    32 x PS f32
//   sPartS/[0,4096), sPartQ/[4096,8192) reuse sA region post-GEMM
// ---------------------------------------------------------------------------
__global__ void k_mlp(const float* __restrict__ b1, const float* __restrict__ b2,
                      const float* __restrict__ lng, const float* __restrict__ lnb,
                      int N) {
    extern __shared__ char sb[];
    __nv_bfloat16* sAhi = (__nv_bfloat16*)(sb);
    float*         sS   = (float*)(sb + 34816);
    float*         sPartS = (float*)(sb);
    float*         sPartQ = (float*)(sb + 4096);

    const int t    = threadIdx.x;
    const int lane = t & 31;
    const int w    = t >> 5;
    const int nodeBase = blockIdx.x * NT;

    // ---- load agg tile, split to bf16 hi/lo ----
    {
        int n  = t >> 3;
        int k0 = (t & 7) * 16;
        int gn = nodeBase + n;
        __nv_bfloat16* rowHi = sAhi + n * PA;
        #pragma unroll
        for (int i = 0; i < 4; ++i) {
            float4 v = make_float4(0.f, 0.f, 0.f, 0.f);
            if (gn < N) v = g_agg4[(size_t)gn * DV + (k0 >> 2) + i];
            int kk = k0 + i * 4;
            float rx, ry, rz, rw;
            uint32_t h0 = bf2_hi(v.x, v.y, rx, ry);
            uint32_t h1 = bf2_hi(v.z, v.w, rz, rw);
            *(uint32_t*)((char*)(rowHi + kk) )            = h0;
            *(uint32_t*)((char*)(rowHi + kk + 2))         = h1;
            *(uint32_t*)((char*)(rowHi + kk) + 8704)      = bf2(rx, ry);
            *(uint32_t*)((char*)(rowHi + kk + 2) + 8704)  = bf2(rz, rw);
        }
    }
    __syncthreads();

    const int mh = w & 1;
    const int nq = w >> 1;
    // ldmatrix base address for this warp (A operand)
    uint32_t aHi = smem_u32(sAhi + (mh * 16 + (lane & 15)) * PA) + (lane >> 4) * 16;

    float acc[16];
    #pragma unroll
    for (int i = 0; i < 16; ++i) acc[i] = 0.f;

    // ---- layer 1: h1 = relu(agg @ W1 + b1) ----
    #pragma unroll
    for (int kt = 0; kt < 8; ++kt) {
        uint32_t ah[4], al[4];
        ldsm_x4(ah, aHi + kt * 32);
        ldsm_x4(al, aHi + 8704 + kt * 32);
        #pragma unroll
        for (int s = 0; s < 4; ++s) {
            uint4 q = g_w1p[(kt * 16 + nq * 4 + s) * 32 + lane];
            mma16816(acc + 4 * s, ah, &q.x);   // ah * wh
            mma16816(acc + 4 * s, ah, &q.z);   // ah * wl
            mma16816(acc + 4 * s, al, &q.x);   // al * wh
        }
    }
    #pragma unroll
    for (int s = 0; s < 4; ++s) {
        int cb = nq * 32 + s * 8 + (lane & 3) * 2;
        int r0 = mh * 16 + (lane >> 2);
        float2 bb = *(const float2*)(b1 + cb);
        float v00 = fmaxf(acc[4*s+0] + bb.x, 0.f);
        float v01 = fmaxf(acc[4*s+1] + bb.y, 0.f);
        float v10 = fmaxf(acc[4*s+2] + bb.x, 0.f);
        float v11 = fmaxf(acc[4*s+3] + bb.y, 0.f);
        float rx, ry;
        char* p0 = (char*)(sAhi + r0 * PA + cb) + 17408;        // sHhi
        char* p1 = (char*)(sAhi + (r0 + 8) * PA + cb) + 17408;
        uint32_t h;
        h = bf2_hi(v00, v01, rx, ry);
        *(uint32_t*)p0 = h; *(uint32_t*)(p0 + 8704) = bf2(rx, ry);
        h = bf2_hi(v10, v11, rx, ry);
        *(uint32_t*)p1 = h; *(uint32_t*)(p1 + 8704) = bf2(rx, ry);
    }
    __syncthreads();

    #pragma unroll
    for (int i = 0; i < 16; ++i) acc[i] = 0.f;

    // ---- layer 2: h2 = h1 @ W2 + b2 ----
    #pragma unroll
    for (int kt = 0; kt < 8; ++kt) {
        uint32_t ah[4], al[4];
        ldsm_x4(ah, aHi + 17408 + kt * 32);
        ldsm_x4(al, aHi + 26112 + kt * 32);
        #pragma unroll
        for (int s = 0; s < 4; ++s) {
            uint4 q = g_w2p[(kt * 16 + nq * 4 + s) * 32 + lane];
            mma16816(acc + 4 * s, ah, &q.x);
            mma16816(acc + 4 * s, ah, &q.z);
            mma16816(acc + 4 * s, al, &q.x);
        }
    }
    #pragma unroll
    for (int s = 0; s < 4; ++s) {
        int cb = nq * 32 + s * 8 + (lane & 3) * 2;
        int r0 = mh * 16 + (lane >> 2);
        float2 bb = *(const float2*)(b2 + cb);
        *(float2*)(sS + r0 * PS + cb)       = make_float2(acc[4*s+0] + bb.x, acc[4*s+1] + bb.y);
        *(float2*)(sS + (r0 + 8) * PS + cb) = make_float2(acc[4*s+2] + bb.x, acc[4*s+3] + bb.y);
    }
    __syncthreads();

    // ---- LayerNorm per node (warp per node, 4 nodes/warp) + column partials ----
    float colS[4] = {0.f, 0.f, 0.f, 0.f};
    float colQ[4] = {0.f, 0.f, 0.f, 0.f};

    #pragma unroll
    for (int r = 0; r < 4; ++r) {
        int n  = w + r * 8;          // 0..31
        int gn = nodeBase + n;
        float v0 = sS[n * PS + lane];
        float v1 = sS[n * PS + lane + 32];
        float v2 = sS[n * PS + lane + 64];
        float v3 = sS[n * PS + lane + 96];
        float s = v0 + v1 + v2 + v3;
        float q = v0*v0 + v1*v1 + v2*v2 + v3*v3;
        #pragma unroll
        for (int o = 16; o; o >>= 1) {
            s += __shfl_xor_sync(0xFFFFFFFFu, s, o);
            q += __shfl_xor_sync(0xFFFFFFFFu, q, o);
        }
        float mu  = s * (1.f / 128.f);
        float var = q * (1.f / 128.f) - mu * mu;
        float inv = rsqrtf(var + EPS);
        if (gn < N) {
            float y0 = (v0 - mu) * inv * lng[lane]      + lnb[lane];
            float y1 = (v1 - mu) * inv * lng[lane + 32] + lnb[lane + 32];
            float y2 = (v2 - mu) * inv * lng[lane + 64] + lnb[lane + 64];
            float y3 = (v3 - mu) * inv * lng[lane + 96] + lnb[lane + 96];
            float* hp = (float*)(g_hln4 + (size_t)gn * DV);
            hp[lane]      = y0;
            hp[lane + 32] = y1;
            hp[lane + 64] = y2;
            hp[lane + 96] = y3;
            colS[0] += y0; colQ[0] += y0 * y0;
            colS[1] += y1; colQ[1] += y1 * y1;
            colS[2] += y2; colQ[2] += y2 * y2;
            colS[3] += y3; colQ[3] += y3 * y3;
        }
    }
    __syncthreads();                 // sA region done -> reuse as partials
    #pragma unroll
    for (int qq = 0; qq < 4; ++qq) {
        sPartS[w * D + lane + 32 * qq] = colS[qq];
        sPartQ[w * D + lane + 32 * qq] = colQ[qq];
    }
    __syncthreads();
    if (t < D) {
        float s = 0.f, q = 0.f;
        #pragma unroll
        for (int w8 = 0; w8 < 8; ++w8) {
            s += sPartS[w8 * D + t];
            q += sPartQ[w8 * D + t];
        }
        atomicAdd(&g_colsum[t], s);
        atomicAdd(&g_colsumsq[t], q);
    }
}

// ---------------------------------------------------------------------------
// K3: finalize GraphNorm stats (1 block, 128 threads)
// ---------------------------------------------------------------------------
__global__ void k_statfin(const float* __restrict__ gnw,
                          const float* __restrict__ gnms,
                          float invN) {
    int c = threadIdx.x;
    float gmu = g_colsum[c] * invN;
    float e2  = g_colsumsq[c] * invN;
    float ms  = gnms[c];
    float gvar = e2 - 2.f * ms * gmu * gmu + ms * ms * gmu * gmu;
    g_mul[c] = rsqrtf(gvar + EPS) * gnw[c];
    g_sub[c] = ms * gmu;
}

// ---------------------------------------------------------------------------
// K4: out = relu((hln - sub) * mul + gn_b) + node_hidden
// ---------------------------------------------------------------------------
__global__ void k_final(const float* __restrict__ nh,
                        const float* __restrict__ gnb,
                        float* __restrict__ out,
                        int total4) {
    int i = blockIdx.x * blockDim.x + threadIdx.x;
    if (i >= total4) return;
    int c4 = (i & (DV - 1)) * 4;
    float4 h = g_hln4[i];
    float4 x = ((const float4*)nh)[i];
    float4 o;
    o.x = fmaxf((h.x - g_sub[c4 + 0]) * g_mul[c4 + 0] + gnb[c4 + 0], 0.f) + x.x;
    o.y = fmaxf((h.y - g_sub[c4 + 1]) * g_mul[c4 + 1] + gnb[c4 + 1], 0.f) + x.y;
    o.z = fmaxf((h.z - g_sub[c4 + 2]) * g_mul[c4 + 2] + gnb[c4 + 2], 0.f) + x.z;
    o.w = fmaxf((h.w - g_sub[c4 + 3]) * g_mul[c4 + 3] + gnb[c4 + 3], 0.f) + x.w;
    ((float4*)out)[i] = o;
}

// ---------------------------------------------------------------------------
extern "C" void kernel_launch(void* const* d_in, const int* in_sizes, int n_in,
                              void* d_out, int out_size) {
    const float* nh   = (const float*)d_in[0];
    const float* eh   = (const float*)d_in[1];
    const float* w1   = (const float*)d_in[2];
    const float* b1   = (const float*)d_in[3];
    const float* w2   = (const float*)d_in[4];
    const float* b2   = (const float*)d_in[5];
    const float* lng  = (const float*)d_in[6];
    const float* lnb  = (const float*)d_in[7];
    const float* gnw  = (const float*)d_in[8];
    const float* gnb  = (const float*)d_in[9];
    const float* gnms = (const float*)d_in[10];
    const int*   ei   = (const int*)d_in[11];

    int N = in_sizes[0] / D;
    int E = in_sizes[1] / D;
    int total4 = N * DV;

    const int SMEM_BYTES = 51712;
    cudaFuncSetAttribute(k_mlp, cudaFuncAttributeMaxDynamicSharedMemorySize, SMEM_BYTES);

    k_zero<<<(total4 + 255) / 256, 256>>>(total4);
    k_prep<<<16, 256>>>(w1, w2);
    k_scatter<<<(E + 7) / 8, 256>>>(nh, eh, ei, E);
    k_mlp<<<(N + NT - 1) / NT, 256, SMEM_BYTES>>>(b1, b2, lng, lnb, N);
    k_statfin<<<1, 128>>>(gnw, gnms, 1.f / (float)N);
    k_final<<<(total4 + 255) / 256, 256>>>(nh, gnb, (float*)d_out, total4);
}